// round 1
// baseline (speedup 1.0000x reference)
#include <cuda_runtime.h>
#include <cstdint>

#define B_DIM 256
#define N_DIM 64
#define T_DIM 4096
#define H_DIM 16
#define TC    256   // t-tile width for the output GEMM

// Scratch (device globals — no allocation allowed)
__device__ float g_energy[B_DIM * N_DIM];
__device__ float g_wT[B_DIM * N_DIM * N_DIM];   // attn weights, transposed [b][j][i]

// ---------- packed f32x2 helpers (Blackwell) ----------
__device__ __forceinline__ unsigned long long pk2(float x, float y) {
    unsigned long long r;
    asm("mov.b64 %0, {%1, %2};" : "=l"(r) : "f"(x), "f"(y));
    return r;
}
__device__ __forceinline__ void ffma2(unsigned long long& d, unsigned long long a, unsigned long long b) {
    asm("fma.rn.f32x2 %0, %1, %2, %0;" : "+l"(d) : "l"(a), "l"(b));
}
__device__ __forceinline__ float2 upk2(unsigned long long v) {
    float2 r;
    asm("mov.b64 {%0, %1}, %2;" : "=f"(r.x), "=f"(r.y) : "l"(v));
    return r;
}

// ---------------------------------------------------------------------------
// Kernel 1: energy[b,n] = var(x[b,n,:]) over T. One warp per (b,n) row.
// ---------------------------------------------------------------------------
__global__ __launch_bounds__(256) void energy_kernel(const float* __restrict__ x) {
    int gw   = (blockIdx.x * blockDim.x + threadIdx.x) >> 5;
    int lane = threadIdx.x & 31;
    if (gw >= B_DIM * N_DIM) return;
    const float4* row = reinterpret_cast<const float4*>(x + (size_t)gw * T_DIM);
    float s = 0.f, ss = 0.f;
#pragma unroll
    for (int k = 0; k < 32; k++) {
        float4 v = row[k * 32 + lane];
        s  += (v.x + v.y) + (v.z + v.w);
        ss += v.x * v.x + v.y * v.y + v.z * v.z + v.w * v.w;
    }
#pragma unroll
    for (int o = 16; o > 0; o >>= 1) {
        s  += __shfl_xor_sync(0xffffffffu, s, o);
        ss += __shfl_xor_sync(0xffffffffu, ss, o);
    }
    if (lane == 0) {
        float m = s * (1.f / T_DIM);
        g_energy[gw] = fmaf(-m, m, ss * (1.f / T_DIM));
    }
}

// ---------------------------------------------------------------------------
// Kernel 2: attention weights. Q,K are rank-1 in energy, so
//   logit[i][j] = 0.25*(e_i*e_j*<Wq,Wk> + e_i*<Wq,bk> + e_j*<bq,Wk> + <bq,bk>)
// diag masked to -1e9, row softmax. One block per batch, one thread per row.
// Writes attn_w to output and a transposed copy for the GEMM kernel.
// ---------------------------------------------------------------------------
__global__ __launch_bounds__(64) void attn_kernel(const float* __restrict__ Wq,
                                                  const float* __restrict__ bq,
                                                  const float* __restrict__ Wk,
                                                  const float* __restrict__ bk,
                                                  float* __restrict__ attn_out) {
    __shared__ float e[N_DIM];
    __shared__ float wsm[N_DIM * 65];  // padded to dodge bank conflicts on transpose
    int b = blockIdx.x;
    int i = threadIdx.x;
    e[i] = g_energy[b * N_DIM + i];

    float c0 = 0.f, c1 = 0.f, c2 = 0.f, c3 = 0.f;
#pragma unroll
    for (int h = 0; h < H_DIM; h++) {
        float wq = Wq[h], bqh = bq[h], wk = Wk[h], bkh = bk[h];
        c0 = fmaf(wq, wk, c0);
        c1 = fmaf(wq, bkh, c1);
        c2 = fmaf(bqh, wk, c2);
        c3 = fmaf(bqh, bkh, c3);
    }
    __syncthreads();

    const float scale = 0.25f;  // H^-0.5, H=16
    float ei = e[i];
    float l[N_DIM];
    float mx = -1e30f;
#pragma unroll
    for (int j = 0; j < N_DIM; j++) {
        float ej = e[j];
        float v = scale * (ei * ej * c0 + ei * c1 + ej * c2 + c3);
        if (j == i) v = -1e9f;
        l[j] = v;
        mx = fmaxf(mx, v);
    }
    float sum = 0.f;
#pragma unroll
    for (int j = 0; j < N_DIM; j++) {
        float w = __expf(l[j] - mx);
        l[j] = w;
        sum += w;
    }
    float inv = 1.f / sum;
#pragma unroll
    for (int j = 0; j < N_DIM; j++)
        wsm[i * 65 + j] = l[j] * inv;
    __syncthreads();

    float* ao = attn_out + (size_t)b * N_DIM * N_DIM;
    float* wt = g_wT + (size_t)b * N_DIM * N_DIM;
#pragma unroll
    for (int k = 0; k < N_DIM; k++) {
        ao[k * 64 + i] = wsm[k * 65 + i];  // w[k][i], coalesced
        wt[k * 64 + i] = wsm[i * 65 + k];  // wT[k][i] = w[i][k], coalesced write
    }
}

// ---------------------------------------------------------------------------
// Kernel 3: out[b,i,t] = sum_j w[b,i,j] * x[b,j,t] + x[b,i,t]
// One block per (b, 256-wide t-tile). SMEM tile of x (64x256) + wT (64x64).
// 256 threads, each owns an 8i x 8t register tile; inner loop over j uses
// packed f32x2 FMAs (2 FMA/instr -> 128 FMA/cyc/SM).
// ---------------------------------------------------------------------------
__global__ __launch_bounds__(256, 2) void out_kernel(const float* __restrict__ x,
                                                     float* __restrict__ out) {
    extern __shared__ float smem[];
    float* xs = smem;               // [64][TC]
    float* wT = smem + N_DIM * TC;  // [64][64]

    int b    = blockIdx.y;
    int tile = blockIdx.x;
    int tid  = threadIdx.x;

    const float* xb = x + (size_t)b * N_DIM * T_DIM + (size_t)tile * TC;
    // Load x tile: 64 rows x 256 cols = 4096 float4, 16 per thread, coalesced.
#pragma unroll
    for (int k = 0; k < 16; k++) {
        int f   = k * 256 + tid;  // float4 index (64 per row)
        int row = f >> 6;
        int c4  = f & 63;
        reinterpret_cast<float4*>(xs + row * TC)[c4] =
            reinterpret_cast<const float4*>(xb + (size_t)row * T_DIM)[c4];
    }
    // Load wT for this batch: 1024 float4.
    const float4* wsrc = reinterpret_cast<const float4*>(g_wT + (size_t)b * N_DIM * N_DIM);
#pragma unroll
    for (int k = 0; k < 4; k++)
        reinterpret_cast<float4*>(wT)[k * 256 + tid] = wsrc[k * 256 + tid];
    __syncthreads();

    int warp = tid >> 5;  // i-group: i in [warp*8, warp*8+8)
    int lane = tid & 31;  // t-group: t offset lane*8

    unsigned long long acc[8][4];
#pragma unroll
    for (int a = 0; a < 8; a++)
#pragma unroll
        for (int p = 0; p < 4; p++) acc[a][p] = 0ull;  // bit pattern of {0.f,0.f}

    const float* xcol = xs + lane * 8;
    const float* wcol = wT + warp * 8;
#pragma unroll 2
    for (int j = 0; j < N_DIM; j++) {
        // x[j][lane*8 .. +7] as 4 packed f32x2 pairs (two LDS.128)
        const ulonglong2* xp = reinterpret_cast<const ulonglong2*>(xcol + j * TC);
        ulonglong2 xa = xp[0];
        ulonglong2 xb2 = xp[1];
        // wT[j][warp*8 .. +7] — broadcast across the warp
        float4 w0 = *reinterpret_cast<const float4*>(wcol + j * 64);
        float4 w1 = *reinterpret_cast<const float4*>(wcol + j * 64 + 4);
        float wv[8] = {w0.x, w0.y, w0.z, w0.w, w1.x, w1.y, w1.z, w1.w};
#pragma unroll
        for (int a = 0; a < 8; a++) {
            unsigned long long wp = pk2(wv[a], wv[a]);
            ffma2(acc[a][0], wp, xa.x);
            ffma2(acc[a][1], wp, xa.y);
            ffma2(acc[a][2], wp, xb2.x);
            ffma2(acc[a][3], wp, xb2.y);
        }
    }

    // Epilogue: residual add from SMEM tile, coalesced float4 stores.
    float* ob = out + (size_t)b * N_DIM * T_DIM + (size_t)tile * TC + lane * 8;
#pragma unroll
    for (int a = 0; a < 8; a++) {
        int i = warp * 8 + a;
        const float4* res = reinterpret_cast<const float4*>(xs + i * TC + lane * 8);
        float4 r0 = res[0], r1 = res[1];
        float2 p0 = upk2(acc[a][0]), p1 = upk2(acc[a][1]);
        float2 p2 = upk2(acc[a][2]), p3 = upk2(acc[a][3]);
        float4 o0 = make_float4(p0.x + r0.x, p0.y + r0.y, p1.x + r0.z, p1.y + r0.w);
        float4 o1 = make_float4(p2.x + r1.x, p2.y + r1.y, p3.x + r1.z, p3.y + r1.w);
        float4* op = reinterpret_cast<float4*>(ob + (size_t)i * T_DIM);
        op[0] = o0;
        op[1] = o1;
    }
}

extern "C" void kernel_launch(void* const* d_in, const int* in_sizes, int n_in,
                              void* d_out, int out_size) {
    const float* x  = (const float*)d_in[0];
    const float* Wq = (const float*)d_in[1];
    const float* bq = (const float*)d_in[2];
    const float* Wk = (const float*)d_in[3];
    const float* bk = (const float*)d_in[4];

    float* out = (float*)d_out;
    // Tuple output (out, attn_w) flattened in order.
    float* attn_out = out + (size_t)B_DIM * N_DIM * T_DIM;

    const int smem_bytes = (N_DIM * TC + N_DIM * N_DIM) * (int)sizeof(float);  // 81920
    cudaFuncSetAttribute(out_kernel, cudaFuncAttributeMaxDynamicSharedMemorySize, smem_bytes);

    // 1 warp per (b,n) row -> 16384 warps -> 2048 blocks of 256
    energy_kernel<<<(B_DIM * N_DIM * 32) / 256, 256>>>(x);
    attn_kernel<<<B_DIM, 64>>>(Wq, bq, Wk, bk, attn_out);
    dim3 grid(T_DIM / TC, B_DIM);
    out_kernel<<<grid, 256, smem_bytes>>>(x, out);
}

// round 3
// speedup vs baseline: 1.4598x; 1.4598x over previous
#include <cuda_runtime.h>
#include <cstdint>

#define B_DIM 256
#define N_DIM 64
#define T_DIM 4096
#define H_DIM 16
#define TS    256   // t-tile per CTA
#define SB    264   // xs SMEM row stride (floats): 264 mod 32 = 8 -> conflict-free B frags
#define SW    68    // ws SMEM row stride (floats)

// Scratch (device global — no allocation allowed)
__device__ float g_energy[B_DIM * N_DIM];

// ---------------------------------------------------------------------------
// Kernel 1: energy[b,n] = var(x[b,n,:]) over T. One warp per (b,n) row.
// ---------------------------------------------------------------------------
__global__ __launch_bounds__(256) void energy_kernel(const float* __restrict__ x) {
    int gw   = (blockIdx.x * blockDim.x + threadIdx.x) >> 5;
    int lane = threadIdx.x & 31;
    if (gw >= B_DIM * N_DIM) return;
    const float4* row = reinterpret_cast<const float4*>(x + (size_t)gw * T_DIM);
    float s = 0.f, ss = 0.f;
#pragma unroll
    for (int k = 0; k < 32; k++) {
        float4 v = row[k * 32 + lane];
        s  += (v.x + v.y) + (v.z + v.w);
        ss += v.x * v.x + v.y * v.y + v.z * v.z + v.w * v.w;
    }
#pragma unroll
    for (int o = 16; o > 0; o >>= 1) {
        s  += __shfl_xor_sync(0xffffffffu, s, o);
        ss += __shfl_xor_sync(0xffffffffu, ss, o);
    }
    if (lane == 0) {
        float m = s * (1.f / T_DIM);
        g_energy[gw] = fmaf(-m, m, ss * (1.f / T_DIM));
    }
}

// ---------------------------------------------------------------------------
// Kernel 2: attn weights (rank-1 logits + softmax) -> attn_out [b][i][j].
// ---------------------------------------------------------------------------
__global__ __launch_bounds__(64) void attn_kernel(const float* __restrict__ Wq,
                                                  const float* __restrict__ bq,
                                                  const float* __restrict__ Wk,
                                                  const float* __restrict__ bk,
                                                  float* __restrict__ attn_out) {
    __shared__ float e[N_DIM];
    __shared__ float wsm[N_DIM * 65];
    int b = blockIdx.x;
    int i = threadIdx.x;
    e[i] = g_energy[b * N_DIM + i];

    float c0 = 0.f, c1 = 0.f, c2 = 0.f, c3 = 0.f;
#pragma unroll
    for (int h = 0; h < H_DIM; h++) {
        float wq = Wq[h], bqh = bq[h], wk = Wk[h], bkh = bk[h];
        c0 = fmaf(wq, wk, c0);
        c1 = fmaf(wq, bkh, c1);
        c2 = fmaf(bqh, wk, c2);
        c3 = fmaf(bqh, bkh, c3);
    }
    __syncthreads();

    const float scale = 0.25f;
    float ei = e[i];
    float l[N_DIM];
    float mx = -1e30f;
#pragma unroll
    for (int j = 0; j < N_DIM; j++) {
        float ej = e[j];
        float v = scale * (ei * ej * c0 + ei * c1 + ej * c2 + c3);
        if (j == i) v = -1e9f;
        l[j] = v;
        mx = fmaxf(mx, v);
    }
    float sum = 0.f;
#pragma unroll
    for (int j = 0; j < N_DIM; j++) {
        float w = __expf(l[j] - mx);
        l[j] = w;
        sum += w;
    }
    float inv = 1.f / sum;
#pragma unroll
    for (int j = 0; j < N_DIM; j++)
        wsm[i * 65 + j] = l[j] * inv;
    __syncthreads();

    float* ao = attn_out + (size_t)b * N_DIM * N_DIM;
#pragma unroll
    for (int k = 0; k < N_DIM; k++)
        ao[k * 64 + i] = wsm[k * 65 + i];  // w[k][i], coalesced
}

// ---------------------------------------------------------------------------
// mma.sync tf32 helpers (sm_80+ PTX -> HMMA, compiles at compute_103)
// ---------------------------------------------------------------------------
__device__ __forceinline__ uint32_t f2tf32(float f) {
    uint32_t r;
    asm("cvt.rna.tf32.f32 %0, %1;" : "=r"(r) : "f"(f));
    return r;
}
__device__ __forceinline__ void mma_tf32(float& d0, float& d1, float& d2, float& d3,
                                         uint32_t a0, uint32_t a1, uint32_t a2, uint32_t a3,
                                         uint32_t b0, uint32_t b1) {
    asm volatile(
        "mma.sync.aligned.m16n8k8.row.col.f32.tf32.tf32.f32 "
        "{%0,%1,%2,%3},{%4,%5,%6,%7},{%8,%9},{%0,%1,%2,%3};"
        : "+f"(d0), "+f"(d1), "+f"(d2), "+f"(d3)
        : "r"(a0), "r"(a1), "r"(a2), "r"(a3), "r"(b0), "r"(b1));
}

// ---------------------------------------------------------------------------
// Kernel 3: out[b,i,t] = sum_j w[b,i,j]*x[b,j,t] + x[b,i,t]
// CTA: (t-tile 256, batch). 8 warps = 4 i-bands (M=16) x 2 t-halves (128 t).
// A = w (tf32, 32 regs/thread, loaded once), B = x tile in SMEM (stride 264,
// conflict-free fragment loads). Residual fp32 from the same SMEM tile.
// ---------------------------------------------------------------------------
__global__ __launch_bounds__(256, 2) void out_kernel(const float* __restrict__ x,
                                                     const float* __restrict__ w,
                                                     float* __restrict__ out) {
    extern __shared__ float smem[];
    float* xs = smem;                 // [64][SB]
    float* ws = smem + N_DIM * SB;    // [64][SW]

    int b    = blockIdx.y;
    int tile = blockIdx.x;
    int tid  = threadIdx.x;
    int wid  = tid >> 5;
    int lane = tid & 31;

    // Load x tile [64 j][256 t] (stride SB), coalesced float4.
    const float* xb = x + (size_t)b * N_DIM * T_DIM + (size_t)tile * TS;
#pragma unroll
    for (int k = 0; k < 16; k++) {
        int f  = k * 256 + tid;   // float4 index; 64 per row
        int j  = f >> 6;
        int c4 = f & 63;
        float4 v = reinterpret_cast<const float4*>(xb + (size_t)j * T_DIM)[c4];
        *reinterpret_cast<float4*>(xs + j * SB + c4 * 4) = v;
    }
    // Load w [64 i][64 j] (stride SW), coalesced float4.
    const float4* wsrc = reinterpret_cast<const float4*>(w + (size_t)b * N_DIM * N_DIM);
#pragma unroll
    for (int k = 0; k < 4; k++) {
        int f  = k * 256 + tid;   // float4 index; 16 per row
        int i  = f >> 4;
        int c4 = f & 15;
        float4 v = wsrc[f];
        *reinterpret_cast<float4*>(ws + i * SW + c4 * 4) = v;
    }
    __syncthreads();

    int i0 = (wid & 3) * 16;   // i band
    int th = wid >> 2;         // t half (0/1)
    int r  = lane >> 2;        // 0..7
    int c  = lane & 3;         // 0..3

    // A fragments: A[m][k] = w[i0+m][k], 8 ksteps x 4 regs, cvt once.
    uint32_t a[8][4];
#pragma unroll
    for (int ks = 0; ks < 8; ks++) {
        int j0 = ks * 8 + c;
        a[ks][0] = f2tf32(ws[(i0 + r) * SW + j0]);
        a[ks][1] = f2tf32(ws[(i0 + r + 8) * SW + j0]);
        a[ks][2] = f2tf32(ws[(i0 + r) * SW + j0 + 4]);
        a[ks][3] = f2tf32(ws[(i0 + r + 8) * SW + j0 + 4]);
    }

    float* ob = out + (size_t)b * N_DIM * T_DIM + (size_t)tile * TS;

#pragma unroll 4
    for (int nt = 0; nt < 16; nt++) {
        int t0 = th * 128 + nt * 8;
        float d0 = 0.f, d1 = 0.f, d2 = 0.f, d3 = 0.f;
#pragma unroll
        for (int ks = 0; ks < 8; ks++) {
            // B frag: b0 at (k=4ks'?, n): row j = ks*8 + c (+4), col t = t0 + r
            uint32_t b0 = f2tf32(xs[(ks * 8 + c) * SB + t0 + r]);
            uint32_t b1 = f2tf32(xs[(ks * 8 + c + 4) * SB + t0 + r]);
            mma_tf32(d0, d1, d2, d3, a[ks][0], a[ks][1], a[ks][2], a[ks][3], b0, b1);
        }
        // Epilogue: residual (fp32 from SMEM) + coalesced STG.64.
        int row0 = i0 + r, row1 = row0 + 8;
        int tcol = t0 + 2 * c;
        float2 res0 = *reinterpret_cast<const float2*>(xs + row0 * SB + tcol);
        float2 res1 = *reinterpret_cast<const float2*>(xs + row1 * SB + tcol);
        float2 o0 = make_float2(d0 + res0.x, d1 + res0.y);
        float2 o1 = make_float2(d2 + res1.x, d3 + res1.y);
        *reinterpret_cast<float2*>(ob + (size_t)row0 * T_DIM + tcol) = o0;
        *reinterpret_cast<float2*>(ob + (size_t)row1 * T_DIM + tcol) = o1;
    }
}

extern "C" void kernel_launch(void* const* d_in, const int* in_sizes, int n_in,
                              void* d_out, int out_size) {
    const float* x  = (const float*)d_in[0];
    const float* Wq = (const float*)d_in[1];
    const float* bq = (const float*)d_in[2];
    const float* Wk = (const float*)d_in[3];
    const float* bk = (const float*)d_in[4];

    float* out = (float*)d_out;
    float* attn_out = out + (size_t)B_DIM * N_DIM * T_DIM;

    const int smem_bytes = (N_DIM * SB + N_DIM * SW) * (int)sizeof(float);  // 84992
    cudaFuncSetAttribute(out_kernel, cudaFuncAttributeMaxDynamicSharedMemorySize, smem_bytes);

    energy_kernel<<<(B_DIM * N_DIM * 32) / 256, 256>>>(x);
    attn_kernel<<<B_DIM, 64>>>(Wq, bq, Wk, bk, attn_out);
    dim3 grid(T_DIM / TS, B_DIM);
    out_kernel<<<grid, 256, smem_bytes>>>(x, attn_out, out);
}

// round 4
// speedup vs baseline: 1.5464x; 1.0593x over previous
#include <cuda_runtime.h>
#include <cstdint>

#define B_DIM 256
#define N_DIM 64
#define T_DIM 4096
#define H_DIM 16
#define TS    256   // t-tile per CTA
#define SB    264   // xs SMEM row stride (floats): mod 32 = 8 -> conflict-free B frags
#define SW    68    // ws SMEM row stride (floats)

// Scratch (device global — no allocation allowed)
__device__ float g_energy[B_DIM * N_DIM];

// ---------------------------------------------------------------------------
// Kernel 1: energy[b,n] = var(x[b,n,:]) over T. One warp per (b,n) row.
// ---------------------------------------------------------------------------
__global__ __launch_bounds__(256) void energy_kernel(const float* __restrict__ x) {
    int gw   = (blockIdx.x * blockDim.x + threadIdx.x) >> 5;
    int lane = threadIdx.x & 31;
    if (gw >= B_DIM * N_DIM) return;
    const float4* row = reinterpret_cast<const float4*>(x + (size_t)gw * T_DIM);
    float s = 0.f, ss = 0.f;
#pragma unroll
    for (int k = 0; k < 32; k++) {
        float4 v = row[k * 32 + lane];
        s  += (v.x + v.y) + (v.z + v.w);
        ss += v.x * v.x + v.y * v.y + v.z * v.z + v.w * v.w;
    }
#pragma unroll
    for (int o = 16; o > 0; o >>= 1) {
        s  += __shfl_xor_sync(0xffffffffu, s, o);
        ss += __shfl_xor_sync(0xffffffffu, ss, o);
    }
    if (lane == 0) {
        float m = s * (1.f / T_DIM);
        g_energy[gw] = fmaf(-m, m, ss * (1.f / T_DIM));
    }
}

// ---------------------------------------------------------------------------
// Kernel 2: attn weights (rank-1 logits + softmax) -> attn_out [b][i][j].
// ---------------------------------------------------------------------------
__global__ __launch_bounds__(64) void attn_kernel(const float* __restrict__ Wq,
                                                  const float* __restrict__ bq,
                                                  const float* __restrict__ Wk,
                                                  const float* __restrict__ bk,
                                                  float* __restrict__ attn_out) {
    __shared__ float e[N_DIM];
    __shared__ float wsm[N_DIM * 65];
    int b = blockIdx.x;
    int i = threadIdx.x;
    e[i] = g_energy[b * N_DIM + i];

    float c0 = 0.f, c1 = 0.f, c2 = 0.f, c3 = 0.f;
#pragma unroll
    for (int h = 0; h < H_DIM; h++) {
        float wq = Wq[h], bqh = bq[h], wk = Wk[h], bkh = bk[h];
        c0 = fmaf(wq, wk, c0);
        c1 = fmaf(wq, bkh, c1);
        c2 = fmaf(bqh, wk, c2);
        c3 = fmaf(bqh, bkh, c3);
    }
    __syncthreads();

    const float scale = 0.25f;
    float ei = e[i];
    float l[N_DIM];
    float mx = -1e30f;
#pragma unroll
    for (int j = 0; j < N_DIM; j++) {
        float ej = e[j];
        float v = scale * (ei * ej * c0 + ei * c1 + ej * c2 + c3);
        if (j == i) v = -1e9f;
        l[j] = v;
        mx = fmaxf(mx, v);
    }
    float sum = 0.f;
#pragma unroll
    for (int j = 0; j < N_DIM; j++) {
        float w = __expf(l[j] - mx);
        l[j] = w;
        sum += w;
    }
    float inv = 1.f / sum;
#pragma unroll
    for (int j = 0; j < N_DIM; j++)
        wsm[i * 65 + j] = l[j] * inv;
    __syncthreads();

    float* ao = attn_out + (size_t)b * N_DIM * N_DIM;
#pragma unroll
    for (int k = 0; k < N_DIM; k++)
        ao[k * 64 + i] = wsm[k * 65 + i];  // w[k][i], coalesced
}

// ---------------------------------------------------------------------------
// mma.sync tf32 helpers (sm_80+ PTX -> HMMA, compiles at compute_103)
// ---------------------------------------------------------------------------
__device__ __forceinline__ uint32_t f2tf32(float f) {
    uint32_t r;
    asm("cvt.rna.tf32.f32 %0, %1;" : "=r"(r) : "f"(f));
    return r;
}
__device__ __forceinline__ void mma_tf32(float& d0, float& d1, float& d2, float& d3,
                                         uint32_t a0, uint32_t a1, uint32_t a2, uint32_t a3,
                                         uint32_t b0, uint32_t b1) {
    asm volatile(
        "mma.sync.aligned.m16n8k8.row.col.f32.tf32.tf32.f32 "
        "{%0,%1,%2,%3},{%4,%5,%6,%7},{%8,%9},{%0,%1,%2,%3};"
        : "+f"(d0), "+f"(d1), "+f"(d2), "+f"(d3)
        : "r"(a0), "r"(a1), "r"(a2), "r"(a3), "r"(b0), "r"(b1));
}

// ---------------------------------------------------------------------------
// Kernel 3: out[b,i,t] = sum_j w[b,i,j]*x[b,j,t] + x[b,i,t]
// CTA: (t-tile 256, batch). 8 warps = 2 i-halves (2x16-row bands) x 4
// t-quarters (64 t each). x tile stored in SMEM PRE-ROUNDED to tf32, used
// for both B fragments (no cvt in mainloop) and the residual add.
// ---------------------------------------------------------------------------
__global__ __launch_bounds__(256, 2) void out_kernel(const float* __restrict__ x,
                                                     const float* __restrict__ w,
                                                     float* __restrict__ out) {
    extern __shared__ float smem[];
    float* xs = smem;                 // [64][SB] (tf32-rounded fp32)
    float* ws = smem + N_DIM * SB;    // [64][SW]

    int b    = blockIdx.y;
    int tile = blockIdx.x;
    int tid  = threadIdx.x;
    int wid  = tid >> 5;
    int lane = tid & 31;

    // Load x tile [64 j][256 t], convert to tf32 once, store (stride SB).
    const float* xb = x + (size_t)b * N_DIM * T_DIM + (size_t)tile * TS;
#pragma unroll
    for (int k = 0; k < 16; k++) {
        int f  = k * 256 + tid;   // float4 index; 64 per row
        int j  = f >> 6;
        int c4 = f & 63;
        float4 v = reinterpret_cast<const float4*>(xb + (size_t)j * T_DIM)[c4];
        uint4 tv = make_uint4(f2tf32(v.x), f2tf32(v.y), f2tf32(v.z), f2tf32(v.w));
        *reinterpret_cast<uint4*>(xs + j * SB + c4 * 4) = tv;
    }
    // Load w [64 i][64 j] (stride SW), coalesced float4.
    const float4* wsrc = reinterpret_cast<const float4*>(w + (size_t)b * N_DIM * N_DIM);
#pragma unroll
    for (int k = 0; k < 4; k++) {
        int f  = k * 256 + tid;   // float4 index; 16 per row
        int i  = f >> 4;
        int c4 = f & 15;
        float4 v = wsrc[f];
        *reinterpret_cast<float4*>(ws + i * SW + c4 * 4) = v;
    }
    __syncthreads();

    int ih = wid & 1;          // i half: rows [ih*32, ih*32+32)
    int tq = wid >> 1;         // t quarter: [tq*64, tq*64+64)
    int i0 = ih * 32;
    int r  = lane >> 2;        // 0..7
    int c  = lane & 3;         // 0..3

    // A fragments: 2 bands x 8 ksteps x 4 regs = 64 regs, cvt once.
    uint32_t a[2][8][4];
#pragma unroll
    for (int band = 0; band < 2; band++) {
        int ib = i0 + band * 16;
#pragma unroll
        for (int ks = 0; ks < 8; ks++) {
            int j0 = ks * 8 + c;
            a[band][ks][0] = f2tf32(ws[(ib + r) * SW + j0]);
            a[band][ks][1] = f2tf32(ws[(ib + r + 8) * SW + j0]);
            a[band][ks][2] = f2tf32(ws[(ib + r) * SW + j0 + 4]);
            a[band][ks][3] = f2tf32(ws[(ib + r + 8) * SW + j0 + 4]);
        }
    }

    float* ob = out + (size_t)b * N_DIM * T_DIM + (size_t)tile * TS;

#pragma unroll
    for (int nt = 0; nt < 8; nt++) {
        int t0 = tq * 64 + nt * 8;
        float d[2][4];
#pragma unroll
        for (int band = 0; band < 2; band++)
#pragma unroll
            for (int q = 0; q < 4; q++) d[band][q] = 0.f;
#pragma unroll
        for (int ks = 0; ks < 8; ks++) {
            // B frag (shared by both bands): rows j = ks*8+c and +4, col t0+r.
            uint32_t b0 = __float_as_uint(xs[(ks * 8 + c) * SB + t0 + r]);
            uint32_t b1 = __float_as_uint(xs[(ks * 8 + c + 4) * SB + t0 + r]);
            mma_tf32(d[0][0], d[0][1], d[0][2], d[0][3],
                     a[0][ks][0], a[0][ks][1], a[0][ks][2], a[0][ks][3], b0, b1);
            mma_tf32(d[1][0], d[1][1], d[1][2], d[1][3],
                     a[1][ks][0], a[1][ks][1], a[1][ks][2], a[1][ks][3], b0, b1);
        }
        // Epilogue: residual (tf32-rounded x from SMEM) + coalesced STG.64.
        int tcol = t0 + 2 * c;
#pragma unroll
        for (int band = 0; band < 2; band++) {
            int row0 = i0 + band * 16 + r, row1 = row0 + 8;
            float2 res0 = *reinterpret_cast<const float2*>(xs + row0 * SB + tcol);
            float2 res1 = *reinterpret_cast<const float2*>(xs + row1 * SB + tcol);
            float2 o0 = make_float2(d[band][0] + res0.x, d[band][1] + res0.y);
            float2 o1 = make_float2(d[band][2] + res1.x, d[band][3] + res1.y);
            *reinterpret_cast<float2*>(ob + (size_t)row0 * T_DIM + tcol) = o0;
            *reinterpret_cast<float2*>(ob + (size_t)row1 * T_DIM + tcol) = o1;
        }
    }
}

extern "C" void kernel_launch(void* const* d_in, const int* in_sizes, int n_in,
                              void* d_out, int out_size) {
    const float* x  = (const float*)d_in[0];
    const float* Wq = (const float*)d_in[1];
    const float* bq = (const float*)d_in[2];
    const float* Wk = (const float*)d_in[3];
    const float* bk = (const float*)d_in[4];

    float* out = (float*)d_out;
    float* attn_out = out + (size_t)B_DIM * N_DIM * T_DIM;

    const int smem_bytes = (N_DIM * SB + N_DIM * SW) * (int)sizeof(float);  // 84992
    cudaFuncSetAttribute(out_kernel, cudaFuncAttributeMaxDynamicSharedMemorySize, smem_bytes);

    energy_kernel<<<(B_DIM * N_DIM * 32) / 256, 256>>>(x);
    attn_kernel<<<B_DIM, 64>>>(Wq, bq, Wk, bk, attn_out);
    dim3 grid(T_DIM / TS, B_DIM);
    out_kernel<<<grid, 256, smem_bytes>>>(x, attn_out, out);
}

// round 6
// speedup vs baseline: 1.7863x; 1.1551x over previous
#include <cuda_runtime.h>
#include <cstdint>

#define B_DIM 256
#define N_DIM 64
#define T_DIM 4096
#define H_DIM 16
#define TS    256   // t-tile per CTA
#define CH    64    // t-chunk width (4 chunks per tile)
#define SBC   72    // x chunk SMEM row stride (floats): mod 32 = 8 -> conflict-free
#define SW    68    // w SMEM row stride (floats)

// Scratch (device global — no allocation allowed)
__device__ float g_energy[B_DIM * N_DIM];

// ======================= helpers =======================
__device__ __forceinline__ uint32_t smem_u32(const void* p) {
    uint32_t a;
    asm("{ .reg .u64 t; cvta.to.shared.u64 t, %1; cvt.u32.u64 %0, t; }" : "=r"(a) : "l"(p));
    return a;
}
__device__ __forceinline__ void cp16(uint32_t smem_dst, const void* gsrc) {
    asm volatile("cp.async.cg.shared.global [%0], [%1], 16;" :: "r"(smem_dst), "l"(gsrc) : "memory");
}
#define CP_COMMIT() asm volatile("cp.async.commit_group;" ::: "memory")
#define CP_WAIT(n)  asm volatile("cp.async.wait_group %0;" :: "n"(n) : "memory")

__device__ __forceinline__ uint32_t f2tf32(float f) {
    uint32_t r;
    asm("cvt.rna.tf32.f32 %0, %1;" : "=r"(r) : "f"(f));
    return r;
}
__device__ __forceinline__ void mma_tf32(float& d0, float& d1, float& d2, float& d3,
                                         uint32_t a0, uint32_t a1, uint32_t a2, uint32_t a3,
                                         uint32_t b0, uint32_t b1) {
    asm volatile(
        "mma.sync.aligned.m16n8k8.row.col.f32.tf32.tf32.f32 "
        "{%0,%1,%2,%3},{%4,%5,%6,%7},{%8,%9},{%0,%1,%2,%3};"
        : "+f"(d0), "+f"(d1), "+f"(d2), "+f"(d3)
        : "r"(a0), "r"(a1), "r"(a2), "r"(a3), "r"(b0), "r"(b1));
}

// ---------------------------------------------------------------------------
// Kernel 1: energy[b,n] = var(x[b,n,:]) over T. One warp per (b,n) row.
// ---------------------------------------------------------------------------
__global__ __launch_bounds__(256) void energy_kernel(const float* __restrict__ x) {
    int gw   = (blockIdx.x * blockDim.x + threadIdx.x) >> 5;
    int lane = threadIdx.x & 31;
    if (gw >= B_DIM * N_DIM) return;
    const float4* row = reinterpret_cast<const float4*>(x + (size_t)gw * T_DIM);
    float s = 0.f, ss = 0.f;
#pragma unroll
    for (int k = 0; k < 32; k++) {
        float4 v = row[k * 32 + lane];
        s  += (v.x + v.y) + (v.z + v.w);
        ss += v.x * v.x + v.y * v.y + v.z * v.z + v.w * v.w;
    }
#pragma unroll
    for (int o = 16; o > 0; o >>= 1) {
        s  += __shfl_xor_sync(0xffffffffu, s, o);
        ss += __shfl_xor_sync(0xffffffffu, ss, o);
    }
    if (lane == 0) {
        float m = s * (1.f / T_DIM);
        g_energy[gw] = fmaf(-m, m, ss * (1.f / T_DIM));
    }
}

// ---------------------------------------------------------------------------
// Kernel 2: attn weights (rank-1 logits + softmax) -> attn_out [b][i][j].
// ---------------------------------------------------------------------------
__global__ __launch_bounds__(64) void attn_kernel(const float* __restrict__ Wq,
                                                  const float* __restrict__ bq,
                                                  const float* __restrict__ Wk,
                                                  const float* __restrict__ bk,
                                                  float* __restrict__ attn_out) {
    __shared__ float e[N_DIM];
    __shared__ float wsm[N_DIM * 65];
    int b = blockIdx.x;
    int i = threadIdx.x;
    e[i] = g_energy[b * N_DIM + i];

    float c0 = 0.f, c1 = 0.f, c2 = 0.f, c3 = 0.f;
#pragma unroll
    for (int h = 0; h < H_DIM; h++) {
        float wq = Wq[h], bqh = bq[h], wk = Wk[h], bkh = bk[h];
        c0 = fmaf(wq, wk, c0);
        c1 = fmaf(wq, bkh, c1);
        c2 = fmaf(bqh, wk, c2);
        c3 = fmaf(bqh, bkh, c3);
    }
    __syncthreads();

    const float scale = 0.25f;
    float ei = e[i];
    float l[N_DIM];
    float mx = -1e30f;
#pragma unroll
    for (int j = 0; j < N_DIM; j++) {
        float ej = e[j];
        float v = scale * (ei * ej * c0 + ei * c1 + ej * c2 + c3);
        if (j == i) v = -1e9f;
        l[j] = v;
        mx = fmaxf(mx, v);
    }
    float sum = 0.f;
#pragma unroll
    for (int j = 0; j < N_DIM; j++) {
        float w = __expf(l[j] - mx);
        l[j] = w;
        sum += w;
    }
    float inv = 1.f / sum;
#pragma unroll
    for (int j = 0; j < N_DIM; j++)
        wsm[i * 65 + j] = l[j] * inv;
    __syncthreads();

    float* ao = attn_out + (size_t)b * N_DIM * N_DIM;
#pragma unroll
    for (int k = 0; k < N_DIM; k++)
        ao[k * 64 + i] = wsm[k * 65 + i];  // w[k][i], coalesced
}

// ---------------------------------------------------------------------------
// Kernel 3: out[b,i,t] = sum_j w[b,i,j]*x[b,j,t] + x[b,i,t]
// CTA: (t-tile 256, batch). x tile split into 4 chunks [64 j][64 t], each in
// its own cp.async-filled buffer (issued up-front; wait+barrier per chunk) so
// DRAM reads overlap MMA + stores. B fragments are raw fp32 bits (tf32 HW
// truncation); residual is exact fp32 from the same SMEM. 8 warps = 2
// i-halves x 4 t-quarters (16 t per warp per chunk).
// ---------------------------------------------------------------------------
__global__ __launch_bounds__(256, 2) void out_kernel(const float* __restrict__ x,
                                                     const float* __restrict__ w,
                                                     float* __restrict__ out) {
    extern __shared__ float smem[];
    float* xs = smem;                       // 4 x [64][SBC]
    float* ws = smem + 4 * N_DIM * SBC;     // [64][SW]

    int b    = blockIdx.y;
    int tile = blockIdx.x;
    int tid  = threadIdx.x;
    int wid  = tid >> 5;
    int lane = tid & 31;

    const float* xb = x + (size_t)b * N_DIM * T_DIM + (size_t)tile * TS;
    const float* wsrc = w + (size_t)b * N_DIM * N_DIM;

    // Group 0: w — 64x64 floats = 1024 float4, 4 per thread (16 float4/row).
#pragma unroll
    for (int k = 0; k < 4; k++) {
        int f  = k * 256 + tid;   // float4 index
        int i  = f >> 4;          // row (16 float4 per row)
        int c4 = f & 15;
        cp16(smem_u32(ws + i * SW + c4 * 4), wsrc + f * 4);
    }
    CP_COMMIT();
    // Groups 1..4: x chunks (each 64 rows x 16 float4 = 1024; 4 per thread).
#pragma unroll
    for (int ch = 0; ch < 4; ch++) {
        float* xc = xs + ch * N_DIM * SBC;
#pragma unroll
        for (int k = 0; k < 4; k++) {
            int f  = k * 256 + tid;
            int j  = f >> 4;
            int c4 = f & 15;
            cp16(smem_u32(xc + j * SBC + c4 * 4),
                 xb + (size_t)j * T_DIM + ch * CH + c4 * 4);
        }
        CP_COMMIT();
    }

    int ih = wid & 1;          // i half: rows [ih*32, +32)
    int tq = wid >> 1;         // t quarter within chunk: [tq*16, +16)
    int i0 = ih * 32;
    int r  = lane >> 2;        // 0..7
    int c  = lane & 3;         // 0..3

    // Wait for w, build A fragments (2 bands x 8 ksteps x 4 regs, rna cvt).
    CP_WAIT(4);
    __syncthreads();
    uint32_t a[2][8][4];
#pragma unroll
    for (int band = 0; band < 2; band++) {
        int ib = i0 + band * 16;
#pragma unroll
        for (int ks = 0; ks < 8; ks++) {
            int j0 = ks * 8 + c;
            a[band][ks][0] = f2tf32(ws[(ib + r) * SW + j0]);
            a[band][ks][1] = f2tf32(ws[(ib + r + 8) * SW + j0]);
            a[band][ks][2] = f2tf32(ws[(ib + r) * SW + j0 + 4]);
            a[band][ks][3] = f2tf32(ws[(ib + r + 8) * SW + j0 + 4]);
        }
    }

    float* ob = out + (size_t)b * N_DIM * T_DIM + (size_t)tile * TS;

#pragma unroll
    for (int ch = 0; ch < 4; ch++) {
        // Chunk ch ready when <= (3-ch) newer groups still pending.
        if (ch == 0) CP_WAIT(3);
        else if (ch == 1) CP_WAIT(2);
        else if (ch == 2) CP_WAIT(1);
        else CP_WAIT(0);
        __syncthreads();

        const float* xc = xs + ch * N_DIM * SBC;
#pragma unroll
        for (int nt = 0; nt < 2; nt++) {
            int t0 = tq * 16 + nt * 8;
            float d[2][4];
#pragma unroll
            for (int band = 0; band < 2; band++)
#pragma unroll
                for (int q = 0; q < 4; q++) d[band][q] = 0.f;
#pragma unroll
            for (int ks = 0; ks < 8; ks++) {
                // Raw fp32 bits -> tf32 truncation in HW.
                uint32_t b0 = __float_as_uint(xc[(ks * 8 + c) * SBC + t0 + r]);
                uint32_t b1 = __float_as_uint(xc[(ks * 8 + c + 4) * SBC + t0 + r]);
                mma_tf32(d[0][0], d[0][1], d[0][2], d[0][3],
                         a[0][ks][0], a[0][ks][1], a[0][ks][2], a[0][ks][3], b0, b1);
                mma_tf32(d[1][0], d[1][1], d[1][2], d[1][3],
                         a[1][ks][0], a[1][ks][1], a[1][ks][2], a[1][ks][3], b0, b1);
            }
            // Epilogue: exact fp32 residual + coalesced STG.64.
            int tcol = t0 + 2 * c;
#pragma unroll
            for (int band = 0; band < 2; band++) {
                int row0 = i0 + band * 16 + r, row1 = row0 + 8;
                float2 res0 = *reinterpret_cast<const float2*>(xc + row0 * SBC + tcol);
                float2 res1 = *reinterpret_cast<const float2*>(xc + row1 * SBC + tcol);
                float2 o0 = make_float2(d[band][0] + res0.x, d[band][1] + res0.y);
                float2 o1 = make_float2(d[band][2] + res1.x, d[band][3] + res1.y);
                int tg = ch * CH + tcol;
                *reinterpret_cast<float2*>(ob + (size_t)row0 * T_DIM + tg) = o0;
                *reinterpret_cast<float2*>(ob + (size_t)row1 * T_DIM + tg) = o1;
            }
        }
    }
}

extern "C" void kernel_launch(void* const* d_in, const int* in_sizes, int n_in,
                              void* d_out, int out_size) {
    const float* x  = (const float*)d_in[0];
    const float* Wq = (const float*)d_in[1];
    const float* bq = (const float*)d_in[2];
    const float* Wk = (const float*)d_in[3];
    const float* bk = (const float*)d_in[4];

    float* out = (float*)d_out;
    float* attn_out = out + (size_t)B_DIM * N_DIM * T_DIM;

    const int smem_bytes = (4 * N_DIM * SBC + N_DIM * SW) * (int)sizeof(float);  // 91136
    cudaFuncSetAttribute(out_kernel, cudaFuncAttributeMaxDynamicSharedMemorySize, smem_bytes);

    energy_kernel<<<(B_DIM * N_DIM * 32) / 256, 256>>>(x);
    attn_kernel<<<B_DIM, 64>>>(Wq, bq, Wk, bk, attn_out);
    dim3 grid(T_DIM / TS, B_DIM);
    out_kernel<<<grid, 256, smem_bytes>>>(x, attn_out, out);
}